// round 17
// baseline (speedup 1.0000x reference)
#include <cuda_runtime.h>
#include <cuda_fp16.h>
#include <cstdint>

#define BATCH 8
#define NSEQ  4096
#define DD    512
#define MROWS (BATCH * NSEQ)   // 32768

// ---------------- scratch (__device__ globals; allocation-free rule) -------
__device__ __half g_qu[MROWS * DD];        // fp16(Q unnormalized)
__device__ __half g_ku[MROWS * DD];        // fp16(K unnormalized)
__device__ __half g_tH[MROWS * DD];        // fp16(T)
__device__ __half g_WHq[DD * DD], g_WHk[DD * DD], g_WHf[DD * DD];
__device__ __half g_WpB[BATCH][DD * DD];   // fp16(Wp * diag(G[b]))
__device__ float g_sqQ[MROWS];             // per-row sum of Q^2 (atomic)
__device__ float g_sqK[MROWS];             // per-row sum of K^2 (atomic)
__device__ float g_Adot[MROWS];            // dot(Qu_row, wg) (atomic)
__device__ float g_invQ[MROWS];
__device__ float g_invK[MROWS];
__device__ float g_A[MROWS];
__device__ float g_Ai[MROWS];              // A * invQ
__device__ float g_nA[BATCH];
__device__ float g_G[BATCH * DD];
__device__ float g_Gp[8][BATCH * DD];

__device__ __forceinline__ uint32_t s2u(const void* p) {
    uint32_t a;
    asm("{ .reg .u64 t; cvta.to.shared.u64 t, %1; cvt.u32.u64 %0, t; }"
        : "=r"(a) : "l"(p));
    return a;
}
__device__ __forceinline__ unsigned short us(__half h) {
    return __half_as_ushort(h);
}
__device__ __forceinline__ uint32_t pk(__half a, __half b) {
    return (uint32_t)us(a) | ((uint32_t)us(b) << 16);
}
__device__ __forceinline__ float lo16(uint32_t u) {
    return __half2float(__ushort_as_half((unsigned short)(u & 0xFFFF)));
}
__device__ __forceinline__ float hi16(uint32_t u) {
    return __half2float(__ushort_as_half((unsigned short)(u >> 16)));
}
__device__ __forceinline__ uint32_t pk2f(float f0, float f1) {
    __half2 h = __floats2half2_rn(f0, f1);   // .x = f0 (low half)
    return *reinterpret_cast<uint32_t*>(&h);
}

#define MMA_F16(d, a, b)                                                     \
    asm volatile(                                                            \
        "mma.sync.aligned.m16n8k16.row.col.f32.f16.f16.f32 "                 \
        "{%0,%1,%2,%3},{%4,%5,%6,%7},{%8,%9},{%0,%1,%2,%3};"                 \
        : "+f"(d[0]), "+f"(d[1]), "+f"(d[2]), "+f"(d[3])                     \
        : "r"(a[0]), "r"(a[1]), "r"(a[2]), "r"(a[3]), "r"(b[0]), "r"(b[1]))

#define LDS64F(f0, f1, addr)                                                 \
    asm volatile("ld.shared.v2.f32 {%0,%1}, [%2];"                           \
                 : "=f"(f0), "=f"(f1) : "r"(addr))

#define CP16(dst, src)                                                       \
    asm volatile("cp.async.ca.shared.global [%0], [%1], 16;"                 \
                 :: "r"(dst), "l"(src))
#define CP_COMMIT() asm volatile("cp.async.commit_group;" ::: "memory")
#define CP_WAIT0()  asm volatile("cp.async.wait_group 0;" ::: "memory")
#define CP_WAIT1()  asm volatile("cp.async.wait_group 1;" ::: "memory")
#define CP_WAIT2()  asm volatile("cp.async.wait_group 2;" ::: "memory")

// ---------------- tensor-core GEMM ----------------------------------------
// Block 128x128, BK=32, 8 warps (4m x 2n), warp 32x64.
// fp16 planes: 48B row stride (12-word, conflict-free scalar LDS).
// fp32 A planes (CFG 0/1): 112B row stride (28-word) — conflict-free for
// ld.shared.v2.f32 fragment fetches, 16B-aligned for cp.async.
constexpr int SUB_H  = 128 * 48;           // 6144
constexpr int SUB_F  = 128 * 112;          // 14336
constexpr int HDR    = 2048;
constexpr int NSTG   = 16;                 // K = 512 / 32

// CFG 0: A=a (fp32),  W=WHq        -> g_qu fp16 (+bq), sumsq->g_sqQ, dot->g_Adot
// CFG 1: A=b (fp32),  W=WHk        -> g_ku fp16 (+bk), sumsq->g_sqK
// CFG 2: A=g_ku fp16, W=WpB[batch] -> g_tH fp16 = invK*acc + bp + invQ*Qu
// CFG 3: A=g_tH fp16, W=WHf        -> outf fp32 (+bf)
template<int CFG>
__global__ __launch_bounds__(256)
void gemmB(const float* __restrict__ Af32, const float* __restrict__ bias,
           const float* __restrict__ wg, float* __restrict__ outf)
{
    constexpr bool AF32 = (CFG <= 1);
    constexpr int APLANE = AF32 ? 2 * SUB_F : 2 * SUB_H;
    constexpr int STAGE  = APLANE + 2 * SUB_H;
    constexpr int NBUF   = AF32 ? 2 : 3;

    const int m0 = blockIdx.y * 128, n0 = blockIdx.x * 128;
    const __half* Ah_ = (CFG == 2) ? g_ku : g_tH;   // fp16 A source (CFG 2/3)
    const __half* Wh_ = (CFG == 0) ? g_WHq : (CFG == 1) ? g_WHk
                       : (CFG == 2) ? g_WpB[m0 >> 12] : g_WHf;

    extern __shared__ char smem[];
    const int t = threadIdx.x, lane = t & 31, w = t >> 5;
    const int wm = (w >> 1) * 32, wn = (w & 1) * 64;
    const int g = lane >> 2, tg = lane & 3;

    if (t < 128) {
        ((float*)smem)[t] = bias[n0 + t];
        if (CFG == 0) ((float*)smem)[128 + t] = wg[n0 + t];
    }

    const uint32_t sbase = s2u(smem) + HDR;

    auto fill = [&](int s, int buf) {
        uint32_t bp = sbase + buf * STAGE;
        if (AF32) {
            // A fp32: 1024 x 16B chunks, 4 per thread
            #pragma unroll
            for (int q = 0; q < 4; q++) {
                int p = q * 256 + t;
                int row = p >> 3, sub = (p >> 2) & 1, cc = p & 3;
                const void* src = Af32 + (m0 + row) * DD + s * 32 + sub * 16 + cc * 4;
                CP16(bp + sub * SUB_F + row * 112 + cc * 16, src);
            }
        } else {
            #pragma unroll
            for (int q = 0; q < 2; q++) {
                int p = q * 256 + t;
                int row = p >> 2, sub = (p >> 1) & 1, cc = p & 1;
                const void* src = Ah_ + (m0 + row) * DD + s * 32 + sub * 16 + cc * 8;
                CP16(bp + sub * SUB_H + row * 48 + cc * 16, src);
            }
        }
        // W fp16: 512 x 16B chunks, 2 per thread
        #pragma unroll
        for (int q = 0; q < 2; q++) {
            int p = q * 256 + t;
            int row = p >> 2, sub = (p >> 1) & 1, cc = p & 1;
            const void* src = Wh_ + (n0 + row) * DD + s * 32 + sub * 16 + cc * 8;
            CP16(bp + APLANE + sub * SUB_H + row * 48 + cc * 16, src);
        }
    };

    float c[2][8][4] = {};

    if (NBUF == 2) {
        fill(0, 0); CP_COMMIT();
    } else {
        fill(0, 0); CP_COMMIT();
        fill(1, 1); CP_COMMIT();
    }

    for (int s = 0; s < NSTG; s++) {
        if (NBUF == 2) {
            if (s + 1 < NSTG) { fill(s + 1, (s + 1) & 1); CP_COMMIT(); CP_WAIT1(); }
            else              { CP_WAIT0(); }
            __syncthreads();
        } else {
            if (s + 2 < NSTG) fill(s + 2, (s + 2) % 3);
            CP_COMMIT();
            CP_WAIT2();
            __syncthreads();
        }

        const uint32_t sb = sbase + (NBUF == 2 ? (s & 1) : (s % 3)) * STAGE;
        #pragma unroll
        for (int kk = 0; kk < 2; kk++) {
            uint32_t ah[2][4], bh[8][2];
            if (AF32) {
                const uint32_t aB = sb + kk * SUB_F;
                #pragma unroll
                for (int i = 0; i < 2; i++) {
                    uint32_t base0 = aB + (wm + i * 16 + g) * 112 + tg * 8;
                    float f0, f1;
                    LDS64F(f0, f1, base0);             ah[i][0] = pk2f(f0, f1);
                    LDS64F(f0, f1, base0 + 8 * 112);   ah[i][1] = pk2f(f0, f1);
                    LDS64F(f0, f1, base0 + 32);        ah[i][2] = pk2f(f0, f1);
                    LDS64F(f0, f1, base0 + 8 * 112 + 32); ah[i][3] = pk2f(f0, f1);
                }
            } else {
                const uint32_t* Awh = (const uint32_t*)(smem + HDR) +
                    ((NBUF == 2 ? (s & 1) : (s % 3)) * STAGE + kk * SUB_H) / 4;
                #pragma unroll
                for (int i = 0; i < 2; i++) {
                    int r = wm + i * 16 + g;
                    ah[i][0] = Awh[r * 12 + tg];
                    ah[i][1] = Awh[(r + 8) * 12 + tg];
                    ah[i][2] = Awh[r * 12 + tg + 4];
                    ah[i][3] = Awh[(r + 8) * 12 + tg + 4];
                }
            }
            {
                const uint32_t* Bwh = (const uint32_t*)(smem + HDR) +
                    ((NBUF == 2 ? (s & 1) : (s % 3)) * STAGE + APLANE + kk * SUB_H) / 4;
                #pragma unroll
                for (int j = 0; j < 8; j++) {
                    int nb = wn + j * 8 + g;
                    bh[j][0] = Bwh[nb * 12 + tg];
                    bh[j][1] = Bwh[nb * 12 + tg + 4];
                }
            }
            #pragma unroll
            for (int i = 0; i < 2; i++)
                #pragma unroll
                for (int j = 0; j < 8; j++)
                    MMA_F16(c[i][j], ah[i], bh[j]);
        }
        __syncthreads();
    }

    // ---- Epilogue ----
    const float* sbias = (const float*)smem;
    const float* swg   = (const float*)smem + 128;
    #pragma unroll
    for (int i = 0; i < 2; i++) {
        const int rm = m0 + wm + i * 16 + g;
        float rs0 = 0.0f, rs8 = 0.0f;      // row sumsq (CFG 0/1)
        float dp0 = 0.0f, dp8 = 0.0f;      // wg dot partials (CFG 0)
        float ik0, iq0, ik8, iq8;
        if (CFG == 2) {
            ik0 = g_invK[rm];     iq0 = g_invQ[rm];
            ik8 = g_invK[rm + 8]; iq8 = g_invQ[rm + 8];
        }
        #pragma unroll
        for (int j = 0; j < 8; j++) {
            const int cn = n0 + wn + j * 8 + 2 * tg;
            const int cl = cn - n0;
            float2 bb = *(const float2*)&sbias[cl];
            if (CFG == 0 || CFG == 1) {
                float v00 = c[i][j][0] + bb.x, v01 = c[i][j][1] + bb.y;
                float v10 = c[i][j][2] + bb.x, v11 = c[i][j][3] + bb.y;
                __half* D = (CFG == 0) ? g_qu : g_ku;
                *(uint32_t*)&D[rm * DD + cn]       = pk2f(v00, v01);
                *(uint32_t*)&D[(rm + 8) * DD + cn] = pk2f(v10, v11);
                rs0 += v00 * v00 + v01 * v01;
                rs8 += v10 * v10 + v11 * v11;
                if (CFG == 0) {
                    float w0 = swg[cl], w1 = swg[cl + 1];
                    dp0 += v00 * w0 + v01 * w1;
                    dp8 += v10 * w0 + v11 * w1;
                }
            } else if (CFG == 2) {
                uint32_t q0 = *(const uint32_t*)&g_qu[rm * DD + cn];
                uint32_t q8 = *(const uint32_t*)&g_qu[(rm + 8) * DD + cn];
                float v00 = c[i][j][0] * ik0 + bb.x + iq0 * lo16(q0);
                float v01 = c[i][j][1] * ik0 + bb.y + iq0 * hi16(q0);
                float v10 = c[i][j][2] * ik8 + bb.x + iq8 * lo16(q8);
                float v11 = c[i][j][3] * ik8 + bb.y + iq8 * hi16(q8);
                *(uint32_t*)&g_tH[rm * DD + cn]       = pk2f(v00, v01);
                *(uint32_t*)&g_tH[(rm + 8) * DD + cn] = pk2f(v10, v11);
            } else {
                *(float2*)&outf[rm * DD + cn] =
                    make_float2(c[i][j][0] + bb.x, c[i][j][1] + bb.y);
                *(float2*)&outf[(rm + 8) * DD + cn] =
                    make_float2(c[i][j][2] + bb.x, c[i][j][3] + bb.y);
            }
        }
        if (CFG == 0 || CFG == 1) {
            rs0 += __shfl_xor_sync(0xFFFFFFFFu, rs0, 1);
            rs0 += __shfl_xor_sync(0xFFFFFFFFu, rs0, 2);
            rs8 += __shfl_xor_sync(0xFFFFFFFFu, rs8, 1);
            rs8 += __shfl_xor_sync(0xFFFFFFFFu, rs8, 2);
            if (CFG == 0) {
                dp0 += __shfl_xor_sync(0xFFFFFFFFu, dp0, 1);
                dp0 += __shfl_xor_sync(0xFFFFFFFFu, dp0, 2);
                dp8 += __shfl_xor_sync(0xFFFFFFFFu, dp8, 1);
                dp8 += __shfl_xor_sync(0xFFFFFFFFu, dp8, 2);
            }
            if (tg == 0) {
                float* SQ = (CFG == 0) ? g_sqQ : g_sqK;
                atomicAdd(&SQ[rm], rs0);
                atomicAdd(&SQ[rm + 8], rs8);
                if (CFG == 0) {
                    atomicAdd(&g_Adot[rm], dp0);
                    atomicAdd(&g_Adot[rm + 8], dp8);
                }
            }
        }
    }
}

constexpr int SMEM_G01 = HDR + 2 * (2 * SUB_F + 2 * SUB_H);   // 83968
constexpr int SMEM_G23 = HDR + 3 * (2 * SUB_H + 2 * SUB_H);   // 75776

// ---------------- weights round + accumulator zeroing ----------------------
constexpr int W4 = DD * DD / 4;   // 65,536

__global__ __launch_bounds__(256)
void roundw3(const float4* __restrict__ Wq, const float4* __restrict__ Wk,
             const float4* __restrict__ Wf)
{
    int idx = blockIdx.x * 256 + threadIdx.x;   // < 3*W4 = 196608
    if (idx < MROWS) {
        g_sqQ[idx] = 0.0f;
        g_sqK[idx] = 0.0f;
        g_Adot[idx] = 0.0f;
        if (idx < BATCH) g_nA[idx] = 0.0f;
    }
    int sel = idx >> 16;
    int off = idx & 0xFFFF;
    const float4* src = (sel == 0) ? Wq : (sel == 1) ? Wk : Wf;
    __half* dst = (sel == 0) ? g_WHq : (sel == 1) ? g_WHk : g_WHf;
    float4 v = src[off];
    ((uint2*)dst)[off] = make_uint2(pk2f(v.x, v.y), pk2f(v.z, v.w));
}

// ---------------- row factors (tiny) ---------------------------------------
__global__ __launch_bounds__(256)
void rowfac()
{
    int r = blockIdx.x * 256 + threadIdx.x;
    float invq = 1.0f / fmaxf(sqrtf(g_sqQ[r]), 1e-12f);
    float invk = 1.0f / fmaxf(sqrtf(g_sqK[r]), 1e-12f);
    g_invQ[r] = invq;
    g_invK[r] = invk;
    float A = g_Adot[r] * invq * 4.419417382415922e-2f;   // 512^-0.5
    g_A[r] = A;
    g_Ai[r] = A * invq;
}

// Pooling phase 1 + fused ||A||^2 partials. grid=(2 dchunk, 8 batch, 8 nsplit)
__global__ __launch_bounds__(128)
void gpoolp()
{
    int b = blockIdx.y;
    int d2 = blockIdx.x * 128 + threadIdx.x;   // uint index: d = 2*d2
    int ns = blockIdx.z;
    int n0 = ns * (NSEQ / 8);

    const uint32_t* qu = (const uint32_t*)g_qu;
    float acc0 = 0.0f, acc1 = 0.0f;
    #pragma unroll 4
    for (int n = n0; n < n0 + NSEQ / 8; n++) {
        float ai = g_Ai[b * NSEQ + n];
        uint32_t u = qu[(b * NSEQ + n) * (DD / 2) + d2];
        acc0 += ai * lo16(u);
        acc1 += ai * hi16(u);
    }
    g_Gp[ns][b * DD + 2 * d2]     = acc0;
    g_Gp[ns][b * DD + 2 * d2 + 1] = acc1;

    if (blockIdx.x == 0) {
        float qv = 0.0f;
        for (int n = n0 + threadIdx.x; n < n0 + NSEQ / 8; n += 128) {
            float av = g_A[b * NSEQ + n];
            qv += av * av;
        }
        #pragma unroll
        for (int off = 16; off > 0; off >>= 1)
            qv += __shfl_xor_sync(0xFFFFFFFFu, qv, off);
        __shared__ float qs[4];
        int lane = threadIdx.x & 31, wid = threadIdx.x >> 5;
        if (lane == 0) qs[wid] = qv;
        __syncthreads();
        if (threadIdx.x == 0)
            atomicAdd(&g_nA[b], qs[0] + qs[1] + qs[2] + qs[3]);
    }
}

__global__ __launch_bounds__(128)
void gpoolr()
{
    int i = blockIdx.x * 128 + threadIdx.x;
    int b = i / DD;
    float s = 0.0f;
    #pragma unroll
    for (int p = 0; p < 8; p++) s += g_Gp[p][i];
    g_G[i] = s * (1.0f / fmaxf(sqrtf(g_nA[b]), 1e-12f));
}

// WpB[b] = fp16(Wp * diag(G[b])) ; grid (W4/256, BATCH), block 256
__global__ __launch_bounds__(256)
void wpscale(const float4* __restrict__ Wp)
{
    int b = blockIdx.y;
    int i = blockIdx.x * 256 + threadIdx.x;
    int d = (i * 4) & (DD - 1);
    float4 v = Wp[i];
    float4 gv = *(const float4*)&g_G[b * DD + d];
    ((uint2*)g_WpB[b])[i] =
        make_uint2(pk2f(v.x * gv.x, v.y * gv.y), pk2f(v.z * gv.z, v.w * gv.w));
}

// ---------------------------------------------------------------------------
extern "C" void kernel_launch(void* const* d_in, const int* in_sizes, int n_in,
                              void* d_out, int out_size)
{
    const float* a  = (const float*)d_in[0];
    const float* b  = (const float*)d_in[1];
    const float* Wq = (const float*)d_in[2];
    const float* bq = (const float*)d_in[3];
    const float* Wk = (const float*)d_in[4];
    const float* bk = (const float*)d_in[5];
    const float* wg = (const float*)d_in[6];
    const float* Wp = (const float*)d_in[7];
    const float* bp = (const float*)d_in[8];
    const float* Wf = (const float*)d_in[9];
    const float* bf = (const float*)d_in[10];
    float* out = (float*)d_out;

    cudaFuncSetAttribute(gemmB<0>, cudaFuncAttributeMaxDynamicSharedMemorySize, SMEM_G01);
    cudaFuncSetAttribute(gemmB<1>, cudaFuncAttributeMaxDynamicSharedMemorySize, SMEM_G01);
    cudaFuncSetAttribute(gemmB<2>, cudaFuncAttributeMaxDynamicSharedMemorySize, SMEM_G23);
    cudaFuncSetAttribute(gemmB<3>, cudaFuncAttributeMaxDynamicSharedMemorySize, SMEM_G23);

    roundw3<<<3 * W4 / 256, 256>>>((const float4*)Wq, (const float4*)Wk,
                                   (const float4*)Wf);

    dim3 gg(4, MROWS / 128);   // (4, 256)

    gemmB<0><<<gg, 256, SMEM_G01>>>(a, bq, wg, nullptr);   // Qu (+sumsq +wg-dot)
    gemmB<1><<<gg, 256, SMEM_G01>>>(b, bk, wg, nullptr);   // Ku (+sumsq)
    rowfac<<<MROWS / 256, 256>>>();                        // invQ/invK/A/Ai
    gpoolp<<<dim3(2, BATCH, 8), 128>>>();                  // G partials + ||A||^2
    gpoolr<<<32, 128>>>();
    wpscale<<<dim3(W4 / 256, BATCH), 256>>>((const float4*)Wp);
    gemmB<2><<<gg, 256, SMEM_G23>>>(nullptr, bp, nullptr, nullptr);  // T
    gemmB<3><<<gg, 256, SMEM_G23>>>(nullptr, bf, nullptr, out);      // out
}